// round 7
// baseline (speedup 1.0000x reference)
#include <cuda_runtime.h>

#define HH 256
#define WW 256
#define NW 8                 // 256 cols / 32
#define NPIX (8 * HH * WW)   // mean denominator
#define NBLK 256             // 32 bands x 8 batch

__device__ float    g_accum = 0.0f;
__device__ unsigned g_done  = 0u;

// ---------------------------------------------------------------------------
// Exact fallback: expanding float-based scan for nearest opposite-class pixel.
// Reached only when d2 >= 25 (prob ~1e-4 of ANY event in this input).
// ---------------------------------------------------------------------------
__device__ __noinline__ float slow_scan(const float* __restrict__ im, int i, int j, bool cls) {
    float best = 1e20f;
    for (int dd = 0; dd < HH; ++dd) {
        float dd2 = (float)(dd * dd);
        if (dd2 >= best) break;
#pragma unroll 1
        for (int s2 = 0; s2 < 2; ++s2) {
            if (s2 && dd == 0) continue;
            int r = s2 ? i - dd : i + dd;
            if (r < 0 || r >= HH) continue;
            const float* row = im + (size_t)r * WW;
            for (int dj = 0; dj < WW; ++dj) {
                float tot = dd2 + (float)(dj * dj);
                if (tot >= best) break;
                int c1 = j + dj, c2 = j - dj;
                if (c1 < WW && ((row[c1] > 0.5f) != cls)) { best = tot; break; }
                if (dj && c2 >= 0 && ((row[c2] > 0.5f) != cls)) { best = tot; break; }
            }
        }
    }
    return best;
}

// ---------------------------------------------------------------------------
// Single fused kernel. Block = (band of 8 rows, batch), 256 threads (8 warps).
// Phase 0: ballot-build mask words for 16-row window (core + /-4 halo) of both
//          images; stage w = (p-t)^2 for core rows in shared.
// Phase 1: threads 0..127 = (image, row, word) -> 5 bit-planes, levels r^2 in
//          {1,2,4,5,8} + gated {9,10,13} + gated {16,17,18,20}.
// Phase 2: warp = row, lane = pixel: acc += w * (s_pred + s_target);
//          s==0 -> exact slow_scan (d2 >= 25).
// Output: last-block finalize (idempotent across graph replays).
// ---------------------------------------------------------------------------
__global__ void __launch_bounds__(256) hd_loss_kernel(const float* __restrict__ pred,
                                                      const float* __restrict__ target,
                                                      float* __restrict__ out) {
    int band = blockIdx.x;          // 0..31
    int b    = blockIdx.y;          // 0..7
    int tid  = threadIdx.x;         // 0..255
    int lane = tid & 31;
    int warp = tid >> 5;            // 0..7

    __shared__ unsigned SM[2][16][10];   // window rows band*8-4..+11, zero-pad cols 0,9
    __shared__ uint4    SP[2][8][NW];    // planes p0..p3
    __shared__ unsigned SP4[2][8][NW];   // plane p4
    __shared__ float    w_sh[8 * WW];    // (p-t)^2 for core rows
    __shared__ float    sred[8];

    const float* pbase = pred   + (size_t)b * HH * WW;
    const float* tbase = target + (size_t)b * HH * WW;

    // zero pads (64 slots: 2 img x 16 rows x 2 pad cols)
    if (tid < 64) {
        int f = tid >> 5, rr = (tid >> 1) & 15, cc = tid & 1;
        SM[f][rr][cc * 9] = 0u;
    }

    // ---------------- Phase 0: ballot mask build + w staging ----------------
#pragma unroll 4
    for (int s = warp; s < 128; s += 8) {   // 16 slots per warp
        int rr  = s >> 3;                   // window row 0..15
        int wwd = s & 7;
        int gi  = band * 8 - 4 + rr;
        float vp = 0.0f, vt = 0.0f;
        if (gi >= 0 && gi < HH) {
            vp = pbase[(size_t)gi * WW + wwd * 32 + lane];
            vt = tbase[(size_t)gi * WW + wwd * 32 + lane];
        }
        unsigned mp = __ballot_sync(0xFFFFFFFFu, vp > 0.5f);
        unsigned mt = __ballot_sync(0xFFFFFFFFu, vt > 0.5f);
        if (lane == 0) {
            SM[0][rr][wwd + 1] = mp;
            SM[1][rr][wwd + 1] = mt;
        }
        if (rr >= 4 && rr < 12) {
            float d = vp - vt;
            w_sh[(rr - 4) * WW + wwd * 32 + lane] = d * d;
        }
    }
    __syncthreads();

    // ---------------- Phase 1: one word-task per thread (128 tasks) ----------------
    if (tid < 128) {
        int f1 = tid >> 6;          // 0 = pred, 1 = target
        int rr = (tid >> 3) & 7;    // core row in band
        int w1 = tid & 7;           // word
        int i1 = band * 8 + rr;
        int sr = rr + 4;
        const unsigned (*M)[10] = SM[f1];

        unsigned W  = M[sr][w1 + 1];
        unsigned l0 = M[sr][w1],         r0  = M[sr][w1 + 2];
        unsigned cU1 = M[sr - 1][w1 + 1], lU1 = M[sr - 1][w1], rU1 = M[sr - 1][w1 + 2];
        unsigned cD1 = M[sr + 1][w1 + 1], lD1 = M[sr + 1][w1], rD1 = M[sr + 1][w1 + 2];

        unsigned mlo1 = (w1 == 0) ? 0xFFFFFFFEu : 0xFFFFFFFFu;
        unsigned mlo2 = (w1 == 0) ? 0xFFFFFFFCu : 0xFFFFFFFFu;
        unsigned mlo3 = (w1 == 0) ? 0xFFFFFFF8u : 0xFFFFFFFFu;
        unsigned mlo4 = (w1 == 0) ? 0xFFFFFFF0u : 0xFFFFFFFFu;
        unsigned mhi1 = (w1 == 7) ? 0x7FFFFFFFu : 0xFFFFFFFFu;
        unsigned mhi2 = (w1 == 7) ? 0x3FFFFFFFu : 0xFFFFFFFFu;
        unsigned mhi3 = (w1 == 7) ? 0x1FFFFFFFu : 0xFFFFFFFFu;
        unsigned mhi4 = (w1 == 7) ? 0x0FFFFFFFu : 0xFFFFFFFFu;
        unsigned rvU1 = (i1 >= 1)   ? 0xFFFFFFFFu : 0u;
        unsigned rvD1 = (i1 <= 254) ? 0xFFFFFFFFu : 0u;
        unsigned rvU2 = (i1 >= 2)   ? 0xFFFFFFFFu : 0u;
        unsigned rvD2 = (i1 <= 253) ? 0xFFFFFFFFu : 0u;
        unsigned rvU3 = (i1 >= 3)   ? 0xFFFFFFFFu : 0u;
        unsigned rvD3 = (i1 <= 252) ? 0xFFFFFFFFu : 0u;
        unsigned rvU4 = (i1 >= 4)   ? 0xFFFFFFFFu : 0u;
        unsigned rvD4 = (i1 <= 251) ? 0xFFFFFFFFu : 0u;

        // s=1: (0,+-1), (+-1,0)
        unsigned h1 = ((W ^ __funnelshift_l(l0, W, 1)) & mlo1)
                    | ((W ^ __funnelshift_r(W, r0, 1)) & mhi1)
                    | ((W ^ cU1) & rvU1) | ((W ^ cD1) & rvD1);
        // s=2: (+-1,+-1)
        unsigned h2 = (((((W ^ __funnelshift_l(lU1, cU1, 1)) & mlo1)
                       | ((W ^ __funnelshift_r(cU1, rU1, 1)) & mhi1)) & rvU1)
                     | ((((W ^ __funnelshift_l(lD1, cD1, 1)) & mlo1)
                       | ((W ^ __funnelshift_r(cD1, rD1, 1)) & mhi1)) & rvD1)) & ~h1;
        unsigned p0 = h1, p1 = h2, p2 = 0u, p3 = 0u, p4 = 0u;
        unsigned U = ~(h1 | h2);
        if (U) {
            unsigned cU2 = M[sr - 2][w1 + 1], lU2 = M[sr - 2][w1], rU2 = M[sr - 2][w1 + 2];
            unsigned cD2 = M[sr + 2][w1 + 1], lD2 = M[sr + 2][w1], rD2 = M[sr + 2][w1 + 2];
            // s=4
            unsigned h4 = (((W ^ __funnelshift_l(l0, W, 2)) & mlo2)
                         | ((W ^ __funnelshift_r(W, r0, 2)) & mhi2)
                         | ((W ^ cU2) & rvU2) | ((W ^ cD2) & rvD2)) & U;
            p2 = h4; U &= ~h4;
            // s=5
            unsigned h5 = (((((W ^ __funnelshift_l(lU1, cU1, 2)) & mlo2)
                           | ((W ^ __funnelshift_r(cU1, rU1, 2)) & mhi2)) & rvU1)
                         | ((((W ^ __funnelshift_l(lD1, cD1, 2)) & mlo2)
                           | ((W ^ __funnelshift_r(cD1, rD1, 2)) & mhi2)) & rvD1)
                         | ((((W ^ __funnelshift_l(lU2, cU2, 1)) & mlo1)
                           | ((W ^ __funnelshift_r(cU2, rU2, 1)) & mhi1)) & rvU2)
                         | ((((W ^ __funnelshift_l(lD2, cD2, 1)) & mlo1)
                           | ((W ^ __funnelshift_r(cD2, rD2, 1)) & mhi1)) & rvD2)) & U;
            p0 |= h5; p2 |= h5; U &= ~h5;
            // s=8
            unsigned h8 = (((((W ^ __funnelshift_l(lU2, cU2, 2)) & mlo2)
                           | ((W ^ __funnelshift_r(cU2, rU2, 2)) & mhi2)) & rvU2)
                         | ((((W ^ __funnelshift_l(lD2, cD2, 2)) & mlo2)
                           | ((W ^ __funnelshift_r(cD2, rD2, 2)) & mhi2)) & rvD2)) & U;
            p3 = h8; U &= ~h8;
            if (U) {
                unsigned cU3 = M[sr - 3][w1 + 1], lU3 = M[sr - 3][w1], rU3 = M[sr - 3][w1 + 2];
                unsigned cD3 = M[sr + 3][w1 + 1], lD3 = M[sr + 3][w1], rD3 = M[sr + 3][w1 + 2];
                // s=9
                unsigned h9 = (((W ^ __funnelshift_l(l0, W, 3)) & mlo3)
                             | ((W ^ __funnelshift_r(W, r0, 3)) & mhi3)
                             | ((W ^ cU3) & rvU3) | ((W ^ cD3) & rvD3)) & U;
                p0 |= h9; p3 |= h9; U &= ~h9;
                // s=10
                unsigned h10 = (((((W ^ __funnelshift_l(lU1, cU1, 3)) & mlo3)
                                | ((W ^ __funnelshift_r(cU1, rU1, 3)) & mhi3)) & rvU1)
                              | ((((W ^ __funnelshift_l(lD1, cD1, 3)) & mlo3)
                                | ((W ^ __funnelshift_r(cD1, rD1, 3)) & mhi3)) & rvD1)
                              | ((((W ^ __funnelshift_l(lU3, cU3, 1)) & mlo1)
                                | ((W ^ __funnelshift_r(cU3, rU3, 1)) & mhi1)) & rvU3)
                              | ((((W ^ __funnelshift_l(lD3, cD3, 1)) & mlo1)
                                | ((W ^ __funnelshift_r(cD3, rD3, 1)) & mhi1)) & rvD3)) & U;
                p1 |= h10; p3 |= h10; U &= ~h10;
                // s=13
                unsigned h13 = (((((W ^ __funnelshift_l(lU2, cU2, 3)) & mlo3)
                                | ((W ^ __funnelshift_r(cU2, rU2, 3)) & mhi3)) & rvU2)
                              | ((((W ^ __funnelshift_l(lD2, cD2, 3)) & mlo3)
                                | ((W ^ __funnelshift_r(cD2, rD2, 3)) & mhi3)) & rvD2)
                              | ((((W ^ __funnelshift_l(lU3, cU3, 2)) & mlo2)
                                | ((W ^ __funnelshift_r(cU3, rU3, 2)) & mhi2)) & rvU3)
                              | ((((W ^ __funnelshift_l(lD3, cD3, 2)) & mlo2)
                                | ((W ^ __funnelshift_r(cD3, rD3, 2)) & mhi2)) & rvD3)) & U;
                p0 |= h13; p2 |= h13; p3 |= h13; U &= ~h13;
                if (U) {
                    unsigned cU4 = M[sr - 4][w1 + 1], lU4 = M[sr - 4][w1], rU4 = M[sr - 4][w1 + 2];
                    unsigned cD4 = M[sr + 4][w1 + 1], lD4 = M[sr + 4][w1], rD4 = M[sr + 4][w1 + 2];
                    // s=16
                    unsigned h16 = (((W ^ __funnelshift_l(l0, W, 4)) & mlo4)
                                  | ((W ^ __funnelshift_r(W, r0, 4)) & mhi4)
                                  | ((W ^ cU4) & rvU4) | ((W ^ cD4) & rvD4)) & U;
                    p4 = h16; U &= ~h16;
                    // s=17
                    unsigned h17 = (((((W ^ __funnelshift_l(lU1, cU1, 4)) & mlo4)
                                    | ((W ^ __funnelshift_r(cU1, rU1, 4)) & mhi4)) & rvU1)
                                  | ((((W ^ __funnelshift_l(lD1, cD1, 4)) & mlo4)
                                    | ((W ^ __funnelshift_r(cD1, rD1, 4)) & mhi4)) & rvD1)
                                  | ((((W ^ __funnelshift_l(lU4, cU4, 1)) & mlo1)
                                    | ((W ^ __funnelshift_r(cU4, rU4, 1)) & mhi1)) & rvU4)
                                  | ((((W ^ __funnelshift_l(lD4, cD4, 1)) & mlo1)
                                    | ((W ^ __funnelshift_r(cD4, rD4, 1)) & mhi1)) & rvD4)) & U;
                    p0 |= h17; p4 |= h17; U &= ~h17;
                    // s=18: (+-3,+-3)
                    unsigned h18 = (((((W ^ __funnelshift_l(lU3, cU3, 3)) & mlo3)
                                    | ((W ^ __funnelshift_r(cU3, rU3, 3)) & mhi3)) & rvU3)
                                  | ((((W ^ __funnelshift_l(lD3, cD3, 3)) & mlo3)
                                    | ((W ^ __funnelshift_r(cD3, rD3, 3)) & mhi3)) & rvD3)) & U;
                    p1 |= h18; p4 |= h18; U &= ~h18;
                    // s=20
                    unsigned h20 = (((((W ^ __funnelshift_l(lU2, cU2, 4)) & mlo4)
                                    | ((W ^ __funnelshift_r(cU2, rU2, 4)) & mhi4)) & rvU2)
                                  | ((((W ^ __funnelshift_l(lD2, cD2, 4)) & mlo4)
                                    | ((W ^ __funnelshift_r(cD2, rD2, 4)) & mhi4)) & rvD2)
                                  | ((((W ^ __funnelshift_l(lU4, cU4, 2)) & mlo2)
                                    | ((W ^ __funnelshift_r(cU4, rU4, 2)) & mhi2)) & rvU4)
                                  | ((((W ^ __funnelshift_l(lD4, cD4, 2)) & mlo2)
                                    | ((W ^ __funnelshift_r(cD4, rD4, 2)) & mhi2)) & rvD4)) & U;
                    p0 |= h20 & 0u;  // 20 = 10100b: p2 + p4
                    p2 |= h20; p4 |= h20;
                    // unresolved pixels keep all-planes-0 -> fallback (d2 >= 25)
                }
            }
        }
        SP [tid >> 6][(tid >> 3) & 7][tid & 7] = make_uint4(p0, p1, p2, p3);
        SP4[tid >> 6][(tid >> 3) & 7][tid & 7] = p4;
    }
    __syncthreads();

    // ---------------- Phase 2: warp = row, lane = pixel ----------------
    int r  = warp;
    int i2 = band * 8 + r;
    float acc = 0.0f;
    unsigned fb = 0u;   // fallback events: bit = ww*2 + side
#pragma unroll
    for (int ww = 0; ww < NW; ++ww) {
        float w = w_sh[r * WW + ww * 32 + lane];
        uint4 P = SP[0][r][ww]; unsigned P4 = SP4[0][r][ww];
        uint4 Q = SP[1][r][ww]; unsigned Q4 = SP4[1][r][ww];
        int sp = (int)((P.x >> lane) & 1u) | ((int)((P.y >> lane) & 1u) << 1)
               | ((int)((P.z >> lane) & 1u) << 2) | ((int)((P.w >> lane) & 1u) << 3)
               | ((int)((P4  >> lane) & 1u) << 4);
        int st = (int)((Q.x >> lane) & 1u) | ((int)((Q.y >> lane) & 1u) << 1)
               | ((int)((Q.z >> lane) & 1u) << 2) | ((int)((Q.w >> lane) & 1u) << 3)
               | ((int)((Q4  >> lane) & 1u) << 4);
        fb |= (sp == 0 ? 1u : 0u) << (ww * 2);
        fb |= (st == 0 ? 2u : 0u) << (ww * 2);
        acc += w * (float)(sp + st);
    }
    // exact fallback (d2 >= 25; ~1e-4 chance of ANY event in this input)
    while (fb) {
        int e = __ffs(fb) - 1; fb &= fb - 1;
        int side = e & 1, ww = e >> 1;
        int col = ww * 32 + lane;
        const float* ib = side ? tbase : pbase;
        bool cls = ib[(size_t)i2 * WW + col] > 0.5f;
        acc += w_sh[r * WW + col] * slow_scan(ib, i2, col, cls);
    }

    // reduce: warp -> block
#pragma unroll
    for (int o = 16; o > 0; o >>= 1) acc += __shfl_xor_sync(0xFFFFFFFFu, acc, o);
    if (lane == 0) sred[warp] = acc;
    __syncthreads();

    // block partial -> global accumulator; last block finalizes + resets
    if (tid == 0) {
        float sum = 0.0f;
#pragma unroll
        for (int k = 0; k < 8; ++k) sum += sred[k];
        atomicAdd(&g_accum, sum);
        __threadfence();
        unsigned prev = atomicAdd(&g_done, 1u);
        if (prev == NBLK - 1) {
            float tot = *(volatile float*)&g_accum;
            *out = tot * (1.0f / (float)NPIX);
            *(volatile float*)&g_accum = 0.0f;      // reset for next graph replay
            *(volatile unsigned*)&g_done = 0u;
            __threadfence();
        }
    }
}

extern "C" void kernel_launch(void* const* d_in, const int* in_sizes, int n_in,
                              void* d_out, int out_size) {
    const float* pred   = (const float*)d_in[0];
    const float* target = (const float*)d_in[1];
    float* out = (float*)d_out;

    hd_loss_kernel<<<dim3(32, 8), 256>>>(pred, target, out);
}

// round 8
// speedup vs baseline: 1.4760x; 1.4760x over previous
#include <cuda_runtime.h>

#define HH 256
#define WW 256
#define NW 8                 // 256 cols / 32
#define NPIX (8 * HH * WW)   // mean denominator
#define NBLK 512             // 64 bands x 8 batch
#define BAND 4               // core rows per block
#define WROWS 10             // window rows = BAND + 2*3

__device__ float    g_accum = 0.0f;
__device__ unsigned g_done  = 0u;

// ---------------------------------------------------------------------------
// Exact fallback: expanding float-based scan for nearest opposite-class pixel.
// Reached only when no opposite pixel lies within r^2 <= 13 (prob ~1e-4 of
// ANY event in this input). Exact for all inputs; 1e20 if none exists.
// ---------------------------------------------------------------------------
__device__ __noinline__ float slow_scan(const float* __restrict__ im, int i, int j, bool cls) {
    float best = 1e20f;
    for (int dd = 0; dd < HH; ++dd) {
        float dd2 = (float)(dd * dd);
        if (dd2 >= best) break;
#pragma unroll 1
        for (int s2 = 0; s2 < 2; ++s2) {
            if (s2 && dd == 0) continue;
            int r = s2 ? i - dd : i + dd;
            if (r < 0 || r >= HH) continue;
            const float* row = im + (size_t)r * WW;
            for (int dj = 0; dj < WW; ++dj) {
                float tot = dd2 + (float)(dj * dj);
                if (tot >= best) break;
                int c1 = j + dj, c2 = j - dj;
                if (c1 < WW && ((row[c1] > 0.5f) != cls)) { best = tot; break; }
                if (dj && c2 >= 0 && ((row[c2] > 0.5f) != cls)) { best = tot; break; }
            }
        }
    }
    return best;
}

// ---------------------------------------------------------------------------
// Single fused kernel. Block = (band of 4 rows, batch), 256 threads (8 warps).
// Phase 0: slot = (window row, word); each warp loads pred+target, ballots
//          masks into shared, stages w = (p-t)^2 for core rows.
// Phase 1: threads 0..63 = (image, row, word) -> 4 bit-planes, levels r^2 in
//          {1,2,4,5,8} + gated {9,10,13}. s = p0+2p1+4p2+8p3.
// Phase 2: warp = (row, word-half), lane = pixel: acc += w*(s_pred+s_target);
//          s==0 -> exact slow_scan.
// Output: last-block finalize (idempotent across graph replays).
// ---------------------------------------------------------------------------
__global__ void __launch_bounds__(256) hd_loss_kernel(const float* __restrict__ pred,
                                                      const float* __restrict__ target,
                                                      float* __restrict__ out) {
    int band = blockIdx.x;          // 0..63
    int b    = blockIdx.y;          // 0..7
    int tid  = threadIdx.x;         // 0..255
    int lane = tid & 31;
    int warp = tid >> 5;            // 0..7

    __shared__ unsigned SM[2][WROWS][10];   // window rows band*4-3..+6, pad cols 0,9
    __shared__ uint4    SP[2][BAND][NW];    // bit-planes p0..p3
    __shared__ float    w_sh[BAND][WW];     // (p-t)^2 core rows
    __shared__ float    sred[8];

    const float* pbase = pred   + (size_t)b * HH * WW;
    const float* tbase = target + (size_t)b * HH * WW;

    // zero pads: 2 img x 10 rows x 2 pad cols = 40 slots
    if (tid < 40) {
        int f = tid / 20, rr = (tid >> 1) % 10, cc = tid & 1;
        SM[f][rr][cc * 9] = 0u;
    }

    // ---------------- Phase 0: loads + ballots + w staging ----------------
    // 80 warp-slots: slot = rr*8 + ww; each warp takes 10 (fully unrolled).
#pragma unroll
    for (int k = 0; k < 10; ++k) {
        int s  = warp + k * 8;      // 0..79
        int rr = s >> 3;            // window row 0..9
        int ww = s & 7;
        int gi = band * BAND - 3 + rr;
        gi = gi < 0 ? 0 : (gi > HH - 1 ? HH - 1 : gi);   // clamped; rv masks fix validity
        float vp = pbase[(size_t)gi * WW + ww * 32 + lane];
        float vt = tbase[(size_t)gi * WW + ww * 32 + lane];
        unsigned mp = __ballot_sync(0xFFFFFFFFu, vp > 0.5f);
        unsigned mt = __ballot_sync(0xFFFFFFFFu, vt > 0.5f);
        if (lane == 0) {
            SM[0][rr][ww + 1] = mp;
            SM[1][rr][ww + 1] = mt;
        }
        if (rr >= 3 && rr < 3 + BAND) {
            float d = vp - vt;
            w_sh[rr - 3][ww * 32 + lane] = d * d;
        }
    }
    __syncthreads();

    // ---------------- Phase 1: one word-task per thread (64 tasks) ----------------
    if (tid < 64) {
        int f1 = tid >> 5;          // 0 = pred, 1 = target
        int rr = (tid >> 3) & 3;    // core row in band
        int w1 = tid & 7;           // word
        int i1 = band * BAND + rr;
        int sr = rr + 3;
        const unsigned (*M)[10] = SM[f1];

        unsigned W   = M[sr][w1 + 1];
        unsigned l0  = M[sr][w1],         r0  = M[sr][w1 + 2];
        unsigned cU1 = M[sr - 1][w1 + 1], lU1 = M[sr - 1][w1], rU1 = M[sr - 1][w1 + 2];
        unsigned cD1 = M[sr + 1][w1 + 1], lD1 = M[sr + 1][w1], rD1 = M[sr + 1][w1 + 2];

        unsigned mlo1 = (w1 == 0) ? 0xFFFFFFFEu : 0xFFFFFFFFu;
        unsigned mlo2 = (w1 == 0) ? 0xFFFFFFFCu : 0xFFFFFFFFu;
        unsigned mlo3 = (w1 == 0) ? 0xFFFFFFF8u : 0xFFFFFFFFu;
        unsigned mhi1 = (w1 == 7) ? 0x7FFFFFFFu : 0xFFFFFFFFu;
        unsigned mhi2 = (w1 == 7) ? 0x3FFFFFFFu : 0xFFFFFFFFu;
        unsigned mhi3 = (w1 == 7) ? 0x1FFFFFFFu : 0xFFFFFFFFu;
        unsigned rvU1 = (i1 >= 1)      ? 0xFFFFFFFFu : 0u;
        unsigned rvD1 = (i1 <= HH - 2) ? 0xFFFFFFFFu : 0u;
        unsigned rvU2 = (i1 >= 2)      ? 0xFFFFFFFFu : 0u;
        unsigned rvD2 = (i1 <= HH - 3) ? 0xFFFFFFFFu : 0u;
        unsigned rvU3 = (i1 >= 3)      ? 0xFFFFFFFFu : 0u;
        unsigned rvD3 = (i1 <= HH - 4) ? 0xFFFFFFFFu : 0u;

        // s=1: (0,+-1), (+-1,0)
        unsigned h1 = ((W ^ __funnelshift_l(l0, W, 1)) & mlo1)
                    | ((W ^ __funnelshift_r(W, r0, 1)) & mhi1)
                    | ((W ^ cU1) & rvU1) | ((W ^ cD1) & rvD1);
        // s=2: (+-1,+-1)
        unsigned h2 = (((((W ^ __funnelshift_l(lU1, cU1, 1)) & mlo1)
                       | ((W ^ __funnelshift_r(cU1, rU1, 1)) & mhi1)) & rvU1)
                     | ((((W ^ __funnelshift_l(lD1, cD1, 1)) & mlo1)
                       | ((W ^ __funnelshift_r(cD1, rD1, 1)) & mhi1)) & rvD1)) & ~h1;
        unsigned p0 = h1, p1 = h2, p2 = 0u, p3 = 0u;
        unsigned U = ~(h1 | h2);
        if (U) {
            unsigned cU2 = M[sr - 2][w1 + 1], lU2 = M[sr - 2][w1], rU2 = M[sr - 2][w1 + 2];
            unsigned cD2 = M[sr + 2][w1 + 1], lD2 = M[sr + 2][w1], rD2 = M[sr + 2][w1 + 2];
            // s=4: (0,+-2), (+-2,0)
            unsigned h4 = (((W ^ __funnelshift_l(l0, W, 2)) & mlo2)
                         | ((W ^ __funnelshift_r(W, r0, 2)) & mhi2)
                         | ((W ^ cU2) & rvU2) | ((W ^ cD2) & rvD2)) & U;
            p2 = h4; U &= ~h4;
            // s=5: (+-1,+-2), (+-2,+-1)
            unsigned h5 = (((((W ^ __funnelshift_l(lU1, cU1, 2)) & mlo2)
                           | ((W ^ __funnelshift_r(cU1, rU1, 2)) & mhi2)) & rvU1)
                         | ((((W ^ __funnelshift_l(lD1, cD1, 2)) & mlo2)
                           | ((W ^ __funnelshift_r(cD1, rD1, 2)) & mhi2)) & rvD1)
                         | ((((W ^ __funnelshift_l(lU2, cU2, 1)) & mlo1)
                           | ((W ^ __funnelshift_r(cU2, rU2, 1)) & mhi1)) & rvU2)
                         | ((((W ^ __funnelshift_l(lD2, cD2, 1)) & mlo1)
                           | ((W ^ __funnelshift_r(cD2, rD2, 1)) & mhi1)) & rvD2)) & U;
            p0 |= h5; p2 |= h5; U &= ~h5;
            // s=8: (+-2,+-2)
            unsigned h8 = (((((W ^ __funnelshift_l(lU2, cU2, 2)) & mlo2)
                           | ((W ^ __funnelshift_r(cU2, rU2, 2)) & mhi2)) & rvU2)
                         | ((((W ^ __funnelshift_l(lD2, cD2, 2)) & mlo2)
                           | ((W ^ __funnelshift_r(cD2, rD2, 2)) & mhi2)) & rvD2)) & U;
            p3 = h8; U &= ~h8;
            if (U) {  // essentially only border words
                unsigned cU3 = M[sr - 3][w1 + 1], lU3 = M[sr - 3][w1], rU3 = M[sr - 3][w1 + 2];
                unsigned cD3 = M[sr + 3][w1 + 1], lD3 = M[sr + 3][w1], rD3 = M[sr + 3][w1 + 2];
                // s=9: (0,+-3), (+-3,0)
                unsigned h9 = (((W ^ __funnelshift_l(l0, W, 3)) & mlo3)
                             | ((W ^ __funnelshift_r(W, r0, 3)) & mhi3)
                             | ((W ^ cU3) & rvU3) | ((W ^ cD3) & rvD3)) & U;
                p0 |= h9; p3 |= h9; U &= ~h9;
                // s=10: (+-1,+-3), (+-3,+-1)
                unsigned h10 = (((((W ^ __funnelshift_l(lU1, cU1, 3)) & mlo3)
                                | ((W ^ __funnelshift_r(cU1, rU1, 3)) & mhi3)) & rvU1)
                              | ((((W ^ __funnelshift_l(lD1, cD1, 3)) & mlo3)
                                | ((W ^ __funnelshift_r(cD1, rD1, 3)) & mhi3)) & rvD1)
                              | ((((W ^ __funnelshift_l(lU3, cU3, 1)) & mlo1)
                                | ((W ^ __funnelshift_r(cU3, rU3, 1)) & mhi1)) & rvU3)
                              | ((((W ^ __funnelshift_l(lD3, cD3, 1)) & mlo1)
                                | ((W ^ __funnelshift_r(cD3, rD3, 1)) & mhi1)) & rvD3)) & U;
                p1 |= h10; p3 |= h10; U &= ~h10;
                // s=13: (+-2,+-3), (+-3,+-2)
                unsigned h13 = (((((W ^ __funnelshift_l(lU2, cU2, 3)) & mlo3)
                                | ((W ^ __funnelshift_r(cU2, rU2, 3)) & mhi3)) & rvU2)
                              | ((((W ^ __funnelshift_l(lD2, cD2, 3)) & mlo3)
                                | ((W ^ __funnelshift_r(cD2, rD2, 3)) & mhi3)) & rvD2)
                              | ((((W ^ __funnelshift_l(lU3, cU3, 2)) & mlo2)
                                | ((W ^ __funnelshift_r(cU3, rU3, 2)) & mhi2)) & rvU3)
                              | ((((W ^ __funnelshift_l(lD3, cD3, 2)) & mlo2)
                                | ((W ^ __funnelshift_r(cD3, rD3, 2)) & mhi2)) & rvD3)) & U;
                p0 |= h13; p2 |= h13; p3 |= h13;
                // unresolved keeps all-planes-0 -> exact fallback
            }
        }
        SP[f1][rr][w1] = make_uint4(p0, p1, p2, p3);
    }
    __syncthreads();

    // ---------------- Phase 2: warp = (row, half), lane = pixel ----------------
    int row  = warp >> 1;           // 0..3
    int half = warp & 1;            // word group
    int i2   = band * BAND + row;
    float acc = 0.0f;
    unsigned fb = 0u;               // fallback events: bit = wq*2 + side
#pragma unroll
    for (int wq = 0; wq < 4; ++wq) {
        int ww = half * 4 + wq;
        float w = w_sh[row][ww * 32 + lane];
        uint4 P = SP[0][row][ww];
        uint4 Q = SP[1][row][ww];
        int sp = (int)((P.x >> lane) & 1u) | ((int)((P.y >> lane) & 1u) << 1)
               | ((int)((P.z >> lane) & 1u) << 2) | ((int)((P.w >> lane) & 1u) << 3);
        int st = (int)((Q.x >> lane) & 1u) | ((int)((Q.y >> lane) & 1u) << 1)
               | ((int)((Q.z >> lane) & 1u) << 2) | ((int)((Q.w >> lane) & 1u) << 3);
        fb |= (sp == 0 ? 1u : 0u) << (wq * 2);
        fb |= (st == 0 ? 2u : 0u) << (wq * 2);
        acc += w * (float)(sp + st);
    }
    // exact fallback (prob ~1e-4 of ANY event in this input)
    while (fb) {
        int e = __ffs(fb) - 1; fb &= fb - 1;
        int side = e & 1, wq = e >> 1;
        int col = (half * 4 + wq) * 32 + lane;
        const float* ib = side ? tbase : pbase;
        bool cls = ib[(size_t)i2 * WW + col] > 0.5f;
        acc += w_sh[row][col] * slow_scan(ib, i2, col, cls);
    }

    // reduce: warp -> block
#pragma unroll
    for (int o = 16; o > 0; o >>= 1) acc += __shfl_xor_sync(0xFFFFFFFFu, acc, o);
    if (lane == 0) sred[warp] = acc;
    __syncthreads();

    // block partial -> global accumulator; last block finalizes + resets
    if (tid == 0) {
        float sum = 0.0f;
#pragma unroll
        for (int k = 0; k < 8; ++k) sum += sred[k];
        atomicAdd(&g_accum, sum);
        __threadfence();
        unsigned prev = atomicAdd(&g_done, 1u);
        if (prev == NBLK - 1) {
            float tot = *(volatile float*)&g_accum;
            *out = tot * (1.0f / (float)NPIX);
            *(volatile float*)&g_accum = 0.0f;      // reset for next graph replay
            *(volatile unsigned*)&g_done = 0u;
            __threadfence();
        }
    }
}

extern "C" void kernel_launch(void* const* d_in, const int* in_sizes, int n_in,
                              void* d_out, int out_size) {
    const float* pred   = (const float*)d_in[0];
    const float* target = (const float*)d_in[1];
    float* out = (float*)d_out;

    hd_loss_kernel<<<dim3(64, 8), 256>>>(pred, target, out);
}